// round 3
// baseline (speedup 1.0000x reference)
#include <cuda_runtime.h>
#include <cstdint>

// LSTM: IN=14, H=28, OUT=2, B=4096, T=512  -- two-phase plan:
//   Phase 1 (time-parallel): xg[bt][j] = {i,f,g,o} pre-activations from x,
//            with both biases folded in. Stored as float4 per (bt, j) so the
//            recurrent kernel reads one coalesced LDG.128 per lane per step.
//   Phase 2 (recurrent): one warp per sequence, ONLY the h-part (56 FFMA2 via
//            packed fma.rn.f32x2), register-capped to 128 so 4 independent
//            warps/SMSP hide each warp's per-step serial tail. No intra-block
//            coupling (round-2 lesson: __syncthreads in the recurrence loses).

#define IN_DIM 14
#define HID    28
#define TSTEPS 512
#define BATCH  4096

typedef unsigned long long u64;

// 4096*512*28 float4 = 940 MB scratch (device-global: the sanctioned path)
__device__ float4 g_xg[(size_t)BATCH * TSTEPS * HID];

__device__ __forceinline__ u64 pack2(float lo, float hi) {
    u64 r; asm("mov.b64 %0, {%1, %2};" : "=l"(r) : "f"(lo), "f"(hi)); return r;
}
__device__ __forceinline__ void unpack2(u64 v, float& lo, float& hi) {
    asm("mov.b64 {%0, %1}, %2;" : "=f"(lo), "=f"(hi) : "l"(v));
}
__device__ __forceinline__ void ffma2(u64& acc, u64 a, u64 b) {
    asm("fma.rn.f32x2 %0, %1, %2, %0;" : "+l"(acc) : "l"(a), "l"(b));
}
__device__ __forceinline__ float fast_ex2(float x) {
    float r; asm("ex2.approx.f32 %0, %1;" : "=f"(r) : "f"(x)); return r;
}
__device__ __forceinline__ float fast_rcp(float x) {
    float r; asm("rcp.approx.f32 %0, %1;" : "=f"(r) : "f"(x)); return r;
}
__device__ __forceinline__ float sigm(float x) {
    return fast_rcp(1.0f + fast_ex2(-1.4426950408889634f * x));
}
__device__ __forceinline__ float tanh_f(float x) {
    return fmaf(2.0f, fast_rcp(1.0f + fast_ex2(-2.8853900817779268f * x)), -1.0f);
}

// ---------------- Phase 1: input projection (time-parallel) ----------------
__global__ void __launch_bounds__(32)
proj_kernel(const float* __restrict__ x,
            const float* __restrict__ W_ih,
            const float* __restrict__ b_ih,
            const float* __restrict__ b_hh)
{
    const int seq  = blockIdx.x;
    const int lane = threadIdx.x;
    const int j    = (lane < HID) ? lane : (HID - 1);

    u64 wih[4][IN_DIM / 2];
    float bias[4];
#pragma unroll
    for (int g = 0; g < 4; g++) {
        const int r = g * HID + j;
        const u64* wi = (const u64*)(W_ih + r * IN_DIM);
#pragma unroll
        for (int p = 0; p < IN_DIM / 2; p++) wih[g][p] = wi[p];
        bias[g] = b_ih[r] + b_hh[r];
    }

    const u64* xq = (const u64*)(x + (size_t)seq * TSTEPS * IN_DIM);
    float4* dst = g_xg + (size_t)seq * TSTEPS * HID;

    u64 xc[7];
#pragma unroll
    for (int p = 0; p < 7; p++) xc[p] = xq[p];

#pragma unroll 1
    for (int t = 0; t < TSTEPS; t++) {
        u64 xn[7];
        {
            const int tn = (t + 1 < TSTEPS) ? (t + 1) : (TSTEPS - 1);
            const u64* xr = xq + tn * 7;
#pragma unroll
            for (int p = 0; p < 7; p++) xn[p] = xr[p];
        }

        u64 A0 = pack2(bias[0], 0.0f);
        u64 A1 = pack2(bias[1], 0.0f);
        u64 A2 = pack2(bias[2], 0.0f);
        u64 A3 = pack2(bias[3], 0.0f);
#pragma unroll
        for (int p = 0; p < 7; p++) {
            ffma2(A0, wih[0][p], xc[p]);
            ffma2(A1, wih[1][p], xc[p]);
            ffma2(A2, wih[2][p], xc[p]);
            ffma2(A3, wih[3][p], xc[p]);
        }
        float lo, hi;
        float4 v;
        unpack2(A0, lo, hi); v.x = lo + hi;
        unpack2(A1, lo, hi); v.y = lo + hi;
        unpack2(A2, lo, hi); v.z = lo + hi;
        unpack2(A3, lo, hi); v.w = lo + hi;

        if (lane < HID) dst[t * HID + j] = v;   // STG.128, coalesced over lanes

#pragma unroll
        for (int p = 0; p < 7; p++) xc[p] = xn[p];
    }
}

// ---------------- Phase 2: recurrence (one warp per sequence) --------------
__global__ void __launch_bounds__(32, 16)   // cap regs at 128 -> 4 warps/SMSP
lstm_rec_kernel(const float* __restrict__ W_hh,
                const float* __restrict__ W_out,
                const float* __restrict__ b_out,
                float* __restrict__ out)
{
    const int seq  = blockIdx.x;
    const int lane = threadIdx.x;
    const int j    = (lane < HID) ? lane : (HID - 1);

    // h-part weights only: 28 u64 = 56 regs
    u64 wh[4][HID / 2];
#pragma unroll
    for (int g = 0; g < 4; g++) {
        const u64* w = (const u64*)(W_hh + (g * HID + j) * HID);
#pragma unroll
        for (int p = 0; p < HID / 2; p++) wh[g][p] = w[p];
    }

    __shared__ __align__(16) float hs[32];
    hs[lane] = 0.0f;
    float h = 0.0f, c = 0.0f;
    __syncwarp();

    const float4* xg = g_xg + (size_t)seq * TSTEPS * HID + j;
    float4 cur = xg[0];

#pragma unroll 1
    for (int t = 0; t < TSTEPS; t++) {
        // prefetch next step's gate inputs (coalesced LDG.128)
        float4 nxt = xg[((t + 1 < TSTEPS) ? (t + 1) : (TSTEPS - 1)) * HID];

        u64 A0 = pack2(cur.x, 0.0f);
        u64 A1 = pack2(cur.y, 0.0f);
        u64 A2 = pack2(cur.z, 0.0f);
        u64 A3 = pack2(cur.w, 0.0f);
#pragma unroll
        for (int q = 0; q < HID / 2; q++) {
            u64 hv = *(const u64*)(hs + 2 * q);   // LDS.64 broadcast
            ffma2(A0, wh[0][q], hv);
            ffma2(A1, wh[1][q], hv);
            ffma2(A2, wh[2][q], hv);
            ffma2(A3, wh[3][q], hv);
        }

        float lo, hi;
        unpack2(A0, lo, hi); const float gi = lo + hi;
        unpack2(A1, lo, hi); const float gf = lo + hi;
        unpack2(A2, lo, hi); const float gg = lo + hi;
        unpack2(A3, lo, hi); const float go = lo + hi;

        const float ia = sigm(gi);
        const float fa = sigm(gf);
        const float ga = tanh_f(gg);
        const float oa = sigm(go);
        c = fmaf(fa, c, ia * ga);
        h = oa * tanh_f(c);

        __syncwarp();
        hs[lane] = h;
        __syncwarp();

        cur = nxt;
    }

    // out[seq, o] = sum_j h_j * W_out[o, j] + b_out[o]
    const float w0 = (lane < HID) ? W_out[j]       : 0.0f;
    const float w1 = (lane < HID) ? W_out[HID + j] : 0.0f;
    float v0 = (lane < HID) ? h * w0 : 0.0f;
    float v1 = (lane < HID) ? h * w1 : 0.0f;
#pragma unroll
    for (int off = 16; off; off >>= 1) {
        v0 += __shfl_down_sync(0xffffffffu, v0, off);
        v1 += __shfl_down_sync(0xffffffffu, v1, off);
    }
    if (lane == 0) {
        out[seq * 2 + 0] = v0 + b_out[0];
        out[seq * 2 + 1] = v1 + b_out[1];
    }
}

extern "C" void kernel_launch(void* const* d_in, const int* in_sizes, int n_in,
                              void* d_out, int out_size)
{
    const float* x     = (const float*)d_in[0];
    const float* W_ih  = (const float*)d_in[1];
    const float* W_hh  = (const float*)d_in[2];
    const float* b_ih  = (const float*)d_in[3];
    const float* b_hh  = (const float*)d_in[4];
    const float* W_out = (const float*)d_in[5];
    const float* b_out = (const float*)d_in[6];
    float* out = (float*)d_out;

    proj_kernel<<<BATCH, 32>>>(x, W_ih, b_ih, b_hh);
    lstm_rec_kernel<<<BATCH, 32>>>(W_hh, W_out, b_out, out);
}